// round 14
// baseline (speedup 1.0000x reference)
#include <cuda_runtime.h>

#define NB 8
#define T 16
#define C 256
#define CM 64
#define AA 32
#define HW 784
#define HWC (HW*C)        /* 200704 */
#define X4F (HWC/4)
#define NSPLIT 4
#define PS (HW/NSPLIT)    /* 196 */
#define SLOTS (NSPLIT*4)  /* 16 partial slots per frame */
#define JPV 17            /* branch jobs per video: 16 local + 1 global */
#define NBR (NB*JPV)      /* 136 branch blocks */
#define APV (HW/4)        /* 196 agg blocks per video */
#define NAGG (APV*NB)     /* 1568 agg blocks */

// Scratch (allocation-free rule: __device__ globals)
__device__ float    g_partial[NB*T*SLOTS*C];   // 2 MB
__device__ float    g_kern[NB*3*C];            // [b][k][c]
__device__ float    g_act[NB*T*C];             // [b][t][c]
__device__ unsigned g_brcnt[NB];               // monotone, mod JPV
__device__ unsigned g_donecnt[NB];             // monotone, mod APV
__device__ unsigned g_flag[NB];                // set by 17th brancher of b, reset by last agg of b

// ---------------- K1: spatial partial sums (EXACT R13 kernel) ---------------
__global__ void k_partial(const float4* __restrict__ x4) {
    int n = blockIdx.x, s = blockIdx.y, tid = threadIdx.x;
    int c4 = tid & 63, pi = tid >> 6;
    const float4* xp = x4 + (size_t)n*X4F + (size_t)(s*PS + pi)*64 + c4;
    float4 a0 = make_float4(0,0,0,0), a1 = a0, a2 = a0, a3 = a0;
    #pragma unroll 4
    for (int i = 0; i < 48; i += 4) {
        float4 v0 = xp[(size_t)(i+0)*256];
        float4 v1 = xp[(size_t)(i+1)*256];
        float4 v2 = xp[(size_t)(i+2)*256];
        float4 v3 = xp[(size_t)(i+3)*256];
        a0.x+=v0.x; a0.y+=v0.y; a0.z+=v0.z; a0.w+=v0.w;
        a1.x+=v1.x; a1.y+=v1.y; a1.z+=v1.z; a1.w+=v1.w;
        a2.x+=v2.x; a2.y+=v2.y; a2.z+=v2.z; a2.w+=v2.w;
        a3.x+=v3.x; a3.y+=v3.y; a3.z+=v3.z; a3.w+=v3.w;
    }
    {   // iteration 48 (49 rows per thread total)
        float4 v = xp[(size_t)48*256];
        a0.x += v.x; a0.y += v.y; a0.z += v.z; a0.w += v.w;
    }
    float4 r;
    r.x = (a0.x + a1.x) + (a2.x + a3.x);
    r.y = (a0.y + a1.y) + (a2.y + a3.y);
    r.z = (a0.z + a1.z) + (a2.z + a3.z);
    r.w = (a0.w + a1.w) + (a2.w + a3.w);
    ((float4*)g_partial)[(size_t)(n*SLOTS + s*4 + pi)*64 + c4] = r;
}

// ---------------- K2: branch (bids 0..135, per-video groups) + agg ----------
__global__ void __launch_bounds__(256) k_branch_agg(
        const float* __restrict__ x, float* __restrict__ y,
        const float* __restrict__ gw1, const float* __restrict__ ggam,
        const float* __restrict__ gbet, const float* __restrict__ gmean,
        const float* __restrict__ gvar, const float* __restrict__ gw2,
        const float* __restrict__ lw1, const float* __restrict__ lgam,
        const float* __restrict__ lbet, const float* __restrict__ lmean,
        const float* __restrict__ lvar, const float* __restrict__ lw2) {
    __shared__ float sm[T*3*C];   // 48 KB; branch aliases the front of it
    int bid = blockIdx.x, tid = threadIdx.x;

    if (bid < NBR) {
        // -------- branch work for video b = bid/JPV, job r = bid%JPV --------
        int b = bid / JPV, r = bid % JPV;
        if (r < T) {
            // local branch (t = r): conv(3,256->64)->bn/relu->conv(1,64->256)->sigmoid
            int t = r;
            float* th_s = sm;            // 768 floats
            float* red  = sm + 768;      // 256 floats
            float* l_s  = sm + 1024;     // 64 floats
            #pragma unroll
            for (int dt = 0; dt < 3; dt++) {
                int tt = t + dt - 1;
                float s = 0.f;
                if (tt >= 0 && tt < T) {
                    #pragma unroll
                    for (int ss = 0; ss < SLOTS; ss++)
                        s += g_partial[(size_t)((b*T + tt)*SLOTS + ss)*C + tid];
                    s *= (1.0f/(float)HW);
                }
                th_s[dt*C + tid] = s;
            }
            __syncthreads();
            int m = tid & 63, part = tid >> 6;
            float acc = 0.f;
            #pragma unroll 8
            for (int i = 0; i < 192; i++) {
                int j = part*192 + i;                 // j = dt*256 + c
                acc += th_s[j] * lw1[j*CM + m];
            }
            red[tid] = acc;
            __syncthreads();
            if (tid < CM) {
                float v = red[tid] + red[tid+64] + red[tid+128] + red[tid+192];
                float inv = rsqrtf(lvar[tid] + 1e-3f);
                v = (v - lmean[tid]) * (lgam[tid] * inv) + lbet[tid];
                l_s[tid] = fmaxf(v, 0.f);
            }
            __syncthreads();
            float o = 0.f;
            #pragma unroll 8
            for (int mm = 0; mm < CM; mm++) o += l_s[mm] * lw2[mm*C + tid];
            g_act[(b*T + t)*C + tid] = 1.f/(1.f + expf(-o));
        } else {
            // global branch: Dense(16->32)->bn/relu->Dense(32->3)->softmax
            int c = tid;
            float th[T];
            #pragma unroll
            for (int t = 0; t < T; t++) {
                float s = 0.f;
                #pragma unroll
                for (int ss = 0; ss < SLOTS; ss++)
                    s += g_partial[(size_t)((b*T + t)*SLOTS + ss)*C + c];
                th[t] = s * (1.0f/(float)HW);
            }
            float lg0 = 0.f, lg1 = 0.f, lg2 = 0.f;
            #pragma unroll 4
            for (int a = 0; a < AA; a++) {
                float g = 0.f;
                #pragma unroll
                for (int t = 0; t < T; t++) g += th[t] * gw1[t*AA + a];
                float inv = rsqrtf(gvar[a] + 1e-3f);
                g = (g - gmean[a]) * (ggam[a] * inv) + gbet[a];
                g = fmaxf(g, 0.f);
                lg0 += g * gw2[a*3 + 0];
                lg1 += g * gw2[a*3 + 1];
                lg2 += g * gw2[a*3 + 2];
            }
            float mx = fmaxf(lg0, fmaxf(lg1, lg2));
            float e0 = expf(lg0 - mx), e1 = expf(lg1 - mx), e2 = expf(lg2 - mx);
            float inv = 1.f/(e0 + e1 + e2);
            g_kern[(b*3 + 0)*C + c] = e0*inv;
            g_kern[(b*3 + 1)*C + c] = e1*inv;
            g_kern[(b*3 + 2)*C + c] = e2*inv;
        }
        __threadfence();
        __syncthreads();
        if (tid == 0) {
            unsigned old = atomicAdd(&g_brcnt[b], 1u);
            if (((old + 1u) % (unsigned)JPV) == 0u)
                atomicExch(&g_flag[b], 1u);   // release: video b branch outputs visible
        }
        return;
    }

    // -------------------- agg work (R2 body; per-video wait) ---------------
    int j  = (NAGG - 1) - (bid - NBR);        // reversed order (L2 tail trick)
    int b  = j / APV;
    int pb = j % APV;
    int c4 = tid & 63, pi = tid >> 6;
    int p = pb*4 + pi;
    size_t base4 = ((size_t)(b*T)*HWC + (size_t)p*C) / 4 + c4;
    const float4* xp = (const float4*)x + base4;
    float4*       yp = (float4*)y + base4;
    const int S4 = X4F;

    // prefetch first two x values — independent of branch outputs, so the
    // DRAM latency overlaps the flag wait below
    float4 xc_pre = xp[0];
    float4 xn_pre = xp[S4];

    if (tid == 0) {
        while (*(volatile unsigned*)&g_flag[b] == 0u) __nanosleep(100);
    }
    __syncthreads();
    __threadfence();                          // acquire g_kern / g_act of video b

    {
        float* coef = sm;                     // 48 KB table
        float k0 = g_kern[(b*3 + 0)*C + tid];
        float k1 = g_kern[(b*3 + 1)*C + tid];
        float k2 = g_kern[(b*3 + 2)*C + tid];
        coef[(0*3 + 0)*C + tid]  = 0.f;
        coef[(15*3 + 2)*C + tid] = 0.f;
        #pragma unroll
        for (int ts = 0; ts < T; ts++) {
            float a = g_act[(b*T + ts)*C + tid];
            #pragma unroll
            for (int k = 0; k < 3; k++) {
                int t = ts + 1 - k;
                if (t >= 0 && t < T) {
                    float kk = (k == 0) ? k0 : ((k == 1) ? k1 : k2);
                    coef[(t*3 + k)*C + tid] = kk * a;
                }
            }
        }
        __syncthreads();
        const float4* cs4 = (const float4*)coef;
        float4 z = make_float4(0.f,0.f,0.f,0.f);
        float4 xm = z;
        float4 xc = xc_pre;
        #pragma unroll
        for (int t = 0; t < T; t++) {
            float4 xn = (t == 0) ? xn_pre
                      : ((t < T-1) ? xp[(size_t)(t+1)*S4] : z);
            float4 c0 = cs4[(t*3 + 0)*64 + c4];
            float4 c1 = cs4[(t*3 + 1)*64 + c4];
            float4 c2 = cs4[(t*3 + 2)*64 + c4];
            float4 o;
            o.x = c0.x*xm.x + c1.x*xc.x + c2.x*xn.x;
            o.y = c0.y*xm.y + c1.y*xc.y + c2.y*xn.y;
            o.z = c0.z*xm.z + c1.z*xc.z + c2.z*xn.z;
            o.w = c0.w*xm.w + c1.w*xc.w + c2.w*xn.w;
            __stcs(yp + (size_t)t*S4, o);
            xm = xc; xc = xn;
        }
    }
    __syncthreads();
    if (tid == 0) {
        unsigned old = atomicAdd(&g_donecnt[b], 1u);
        if (((old + 1u) % (unsigned)APV) == 0u)
            atomicExch(&g_flag[b], 0u);       // reset video b flag for next replay
    }
}

extern "C" void kernel_launch(void* const* d_in, const int* in_sizes, int n_in,
                              void* d_out, int out_size) {
    const float* x       = (const float*)d_in[0];
    const float* gw1     = (const float*)d_in[1];
    const float* ggamma  = (const float*)d_in[2];
    const float* gbeta   = (const float*)d_in[3];
    const float* gmean   = (const float*)d_in[4];
    const float* gvar    = (const float*)d_in[5];
    const float* gw2     = (const float*)d_in[6];
    const float* lw1     = (const float*)d_in[7];
    const float* lgamma  = (const float*)d_in[8];
    const float* lbeta   = (const float*)d_in[9];
    const float* lmean   = (const float*)d_in[10];
    const float* lvar    = (const float*)d_in[11];
    const float* lw2     = (const float*)d_in[12];
    float* y = (float*)d_out;

    k_partial<<<dim3(NB*T, NSPLIT), 256>>>((const float4*)x);
    k_branch_agg<<<NBR + NAGG, 256>>>(x, y,
                                      gw1, ggamma, gbeta, gmean, gvar, gw2,
                                      lw1, lgamma, lbeta, lmean, lvar, lw2);
}

// round 15
// speedup vs baseline: 1.0606x; 1.0606x over previous
#include <cuda_runtime.h>

#define NB 8
#define T 16
#define C 256
#define CM 64
#define AA 32
#define HW 784
#define HWC (HW*C)        /* 200704 */
#define X4F (HWC/4)
#define NSPLIT 4
#define PS (HW/NSPLIT)    /* 196 */
#define SLOTS (NSPLIT*4)  /* 16 partial slots per frame */
#define NPART 512         /* partial blocks: 128 frames x 4 segments */
#define PPV 64            /* partial blocks per video */
#define JPV 17            /* branch jobs per video */
#define NBR (NB*JPV)      /* 136 branch blocks */

// Scratch (allocation-free rule: __device__ globals)
__device__ float    g_partial[NB*T*SLOTS*C];   // 2 MB
__device__ float    g_kern[NB*3*C];            // [b][k][c]
__device__ float    g_act[NB*T*C];             // [b][t][c]
__device__ unsigned g_pcnt[NB];                // monotone, mod PPV
__device__ unsigned g_bdone[NB];               // monotone, mod JPV
__device__ unsigned g_pflag[NB];               // set by 64th partial, reset by 17th brancher

// ---------------- Node 1: k_partial bodies + spin-gated branch blocks ------
__global__ void __launch_bounds__(256) k_partial_branch(const float4* __restrict__ x4,
        const float* __restrict__ gw1, const float* __restrict__ ggam,
        const float* __restrict__ gbet, const float* __restrict__ gmean,
        const float* __restrict__ gvar, const float* __restrict__ gw2,
        const float* __restrict__ lw1, const float* __restrict__ lgam,
        const float* __restrict__ lbet, const float* __restrict__ lmean,
        const float* __restrict__ lvar, const float* __restrict__ lw2) {
    int bid = blockIdx.x, tid = threadIdx.x;

    if (bid < NPART) {
        // ---------------- EXACT R2 k_partial body ----------------
        int n = bid & 127, s = bid >> 7;       // preserves R2 issue order
        int c4 = tid & 63, pi = tid >> 6;
        const float4* xp = x4 + (size_t)n*X4F + (size_t)(s*PS + pi)*64 + c4;
        float4 a0 = make_float4(0,0,0,0), a1 = a0, a2 = a0, a3 = a0;
        #pragma unroll 4
        for (int i = 0; i < 48; i += 4) {
            float4 v0 = xp[(size_t)(i+0)*256];
            float4 v1 = xp[(size_t)(i+1)*256];
            float4 v2 = xp[(size_t)(i+2)*256];
            float4 v3 = xp[(size_t)(i+3)*256];
            a0.x+=v0.x; a0.y+=v0.y; a0.z+=v0.z; a0.w+=v0.w;
            a1.x+=v1.x; a1.y+=v1.y; a1.z+=v1.z; a1.w+=v1.w;
            a2.x+=v2.x; a2.y+=v2.y; a2.z+=v2.z; a2.w+=v2.w;
            a3.x+=v3.x; a3.y+=v3.y; a3.z+=v3.z; a3.w+=v3.w;
        }
        {   // 49th row per thread
            float4 v = xp[(size_t)48*256];
            a0.x+=v.x; a0.y+=v.y; a0.z+=v.z; a0.w+=v.w;
        }
        float4 r;
        r.x = (a0.x+a1.x)+(a2.x+a3.x);
        r.y = (a0.y+a1.y)+(a2.y+a3.y);
        r.z = (a0.z+a1.z)+(a2.z+a3.z);
        r.w = (a0.w+a1.w)+(a2.w+a3.w);
        ((float4*)g_partial)[(size_t)(n*SLOTS + s*4 + pi)*64 + c4] = r;
        __threadfence();
        __syncthreads();
        if (tid == 0) {
            int b = n >> 4;
            unsigned old = atomicAdd(&g_pcnt[b], 1u);
            if (((old + 1u) % (unsigned)PPV) == 0u)
                atomicExch(&g_pflag[b], 1u);   // release: video b partials visible
        }
        return;
    }

    // ---------------- branch blocks: spin for their video, then R2 bodies ---
    int j = bid - NPART;                       // 0..135
    int b = j / JPV, r = j % JPV;
    if (tid == 0) {
        while (*(volatile unsigned*)&g_pflag[b] == 0u) __nanosleep(100);
    }
    __syncthreads();
    __threadfence();                           // acquire video b partials

    if (r < T) {
        // local branch (t=r): conv(3,256->64)->bn/relu->conv(1,64->256)->sigmoid
        int t = r;
        __shared__ float th_s[3*C];
        __shared__ float red[256];
        __shared__ float l_s[CM];
        #pragma unroll
        for (int dt = 0; dt < 3; dt++) {
            int tt = t + dt - 1;
            float s = 0.f;
            if (tt >= 0 && tt < T) {
                #pragma unroll
                for (int ss = 0; ss < SLOTS; ss++)
                    s += g_partial[(size_t)((b*T + tt)*SLOTS + ss)*C + tid];
                s *= (1.0f/(float)HW);
            }
            th_s[dt*C + tid] = s;
        }
        __syncthreads();
        int m = tid & 63, part = tid >> 6;
        float acc = 0.f;
        #pragma unroll 8
        for (int i = 0; i < 192; i++) {
            int jj = part*192 + i;             // jj = dt*256 + c
            acc += th_s[jj] * lw1[jj*CM + m];
        }
        red[tid] = acc;
        __syncthreads();
        if (tid < CM) {
            float v = red[tid] + red[tid+64] + red[tid+128] + red[tid+192];
            float inv = rsqrtf(lvar[tid] + 1e-3f);
            v = (v - lmean[tid]) * (lgam[tid] * inv) + lbet[tid];
            l_s[tid] = fmaxf(v, 0.f);
        }
        __syncthreads();
        float o = 0.f;
        #pragma unroll 8
        for (int mm = 0; mm < CM; mm++) o += l_s[mm] * lw2[mm*C + tid];
        g_act[(b*T + t)*C + tid] = 1.f/(1.f + expf(-o));
    } else {
        // global branch: Dense(16->32)->bn/relu->Dense(32->3)->softmax
        int c = tid;
        float th[T];
        #pragma unroll
        for (int t = 0; t < T; t++) {
            float s = 0.f;
            #pragma unroll
            for (int ss = 0; ss < SLOTS; ss++)
                s += g_partial[(size_t)((b*T + t)*SLOTS + ss)*C + c];
            th[t] = s * (1.0f/(float)HW);
        }
        float lg0 = 0.f, lg1 = 0.f, lg2 = 0.f;
        #pragma unroll 4
        for (int a = 0; a < AA; a++) {
            float g = 0.f;
            #pragma unroll
            for (int t = 0; t < T; t++) g += th[t] * gw1[t*AA + a];
            float inv = rsqrtf(gvar[a] + 1e-3f);
            g = (g - gmean[a]) * (ggam[a] * inv) + gbet[a];
            g = fmaxf(g, 0.f);
            lg0 += g * gw2[a*3 + 0];
            lg1 += g * gw2[a*3 + 1];
            lg2 += g * gw2[a*3 + 2];
        }
        float mx = fmaxf(lg0, fmaxf(lg1, lg2));
        float e0 = expf(lg0 - mx), e1 = expf(lg1 - mx), e2 = expf(lg2 - mx);
        float inv = 1.f/(e0 + e1 + e2);
        g_kern[(b*3 + 0)*C + c] = e0*inv;
        g_kern[(b*3 + 1)*C + c] = e1*inv;
        g_kern[(b*3 + 2)*C + c] = e2*inv;
    }
    __syncthreads();
    if (tid == 0) {
        unsigned old = atomicAdd(&g_bdone[b], 1u);
        if (((old + 1u) % (unsigned)JPV) == 0u)
            atomicExch(&g_pflag[b], 0u);       // reset for next replay
    }
}

// ---------------- Node 2: EXACT R2 k_agg (proven 30us) ---------------------
__global__ void k_agg(const float* __restrict__ x, float* __restrict__ y) {
    int tid = threadIdx.x;
    int b  = (NB - 1) - blockIdx.y;
    int pb = (gridDim.x - 1) - blockIdx.x;
    int c4 = tid & 63, pi = tid >> 6;
    int p = pb*4 + pi;
    __shared__ float coef[T*3*C];  // 48 KB
    float k0 = g_kern[(b*3 + 0)*C + tid];
    float k1 = g_kern[(b*3 + 1)*C + tid];
    float k2 = g_kern[(b*3 + 2)*C + tid];
    coef[(0*3 + 0)*C + tid]  = 0.f;
    coef[(15*3 + 2)*C + tid] = 0.f;
    #pragma unroll
    for (int ts = 0; ts < T; ts++) {
        float a = g_act[(b*T + ts)*C + tid];
        #pragma unroll
        for (int k = 0; k < 3; k++) {
            int t = ts + 1 - k;
            if (t >= 0 && t < T) {
                float kk = (k == 0) ? k0 : ((k == 1) ? k1 : k2);
                coef[(t*3 + k)*C + tid] = kk * a;
            }
        }
    }
    __syncthreads();
    const float4* cs4 = (const float4*)coef;
    size_t base4 = ((size_t)(b*T)*HWC + (size_t)p*C) / 4 + c4;
    const float4* xp = (const float4*)x + base4;
    float4*       yp = (float4*)y + base4;
    const int S4 = X4F;
    float4 xm = make_float4(0.f,0.f,0.f,0.f);
    float4 xc = xp[0];
    #pragma unroll
    for (int t = 0; t < T; t++) {
        float4 xn = (t < T-1) ? xp[(size_t)(t+1)*S4] : make_float4(0.f,0.f,0.f,0.f);
        float4 c0 = cs4[(t*3 + 0)*64 + c4];
        float4 c1 = cs4[(t*3 + 1)*64 + c4];
        float4 c2 = cs4[(t*3 + 2)*64 + c4];
        float4 o;
        o.x = c0.x*xm.x + c1.x*xc.x + c2.x*xn.x;
        o.y = c0.y*xm.y + c1.y*xc.y + c2.y*xn.y;
        o.z = c0.z*xm.z + c1.z*xc.z + c2.z*xn.z;
        o.w = c0.w*xm.w + c1.w*xc.w + c2.w*xn.w;
        __stcs(yp + (size_t)t*S4, o);
        xm = xc; xc = xn;
    }
}

extern "C" void kernel_launch(void* const* d_in, const int* in_sizes, int n_in,
                              void* d_out, int out_size) {
    const float* x       = (const float*)d_in[0];
    const float* gw1     = (const float*)d_in[1];
    const float* ggamma  = (const float*)d_in[2];
    const float* gbeta   = (const float*)d_in[3];
    const float* gmean   = (const float*)d_in[4];
    const float* gvar    = (const float*)d_in[5];
    const float* gw2     = (const float*)d_in[6];
    const float* lw1     = (const float*)d_in[7];
    const float* lgamma  = (const float*)d_in[8];
    const float* lbeta   = (const float*)d_in[9];
    const float* lmean   = (const float*)d_in[10];
    const float* lvar    = (const float*)d_in[11];
    const float* lw2     = (const float*)d_in[12];
    float* y = (float*)d_out;

    k_partial_branch<<<NPART + NBR, 256>>>((const float4*)x,
                                  gw1, ggamma, gbeta, gmean, gvar, gw2,
                                  lw1, lgamma, lbeta, lmean, lvar, lw2);
    k_agg<<<dim3(HW/4, NB), 256>>>(x, y);
}